// round 17
// baseline (speedup 1.0000x reference)
#include <cuda_runtime.h>
#include <cuda_bf16.h>
#include <cuda_fp16.h>
#include <math.h>
#include <stdint.h>

#define NB   64
#define PP   256
#define DV   1024
#define DT   768
#define SS   512
#define NSEG 32
#define PPT  8
#define MTOT 2048          // NB*NSEG rows
#define KA   1024          // A row length (fp16)
#define KB   1024          // B row length (fp16 W^T)
#define KITER 16           // K-iterations per CTA (BK=32, half of K=1024)
#define STAGES 5

// ---------------- scratch --------------------------------------------------
static __device__ __half g_ah[MTOT * KA];              // 4 MB
static __device__ __half g_bh[DT * KB];                // 1.5 MB
static __device__ float g_part0[MTOT * DT];            // z=0: K lo half
static __device__ float g_part1[MTOT * DT];            // z=1: K hi half
static __device__ float g_pool[NB * DT];               // unnormalized pooled means
static __device__ float g_sim[NB * NB];
static __device__ int   g_rank[NB * SS];
static __device__ int   g_pos[NB * NSEG];              // inverse map: seg -> seq pos

__device__ __forceinline__ uint32_t smem_u32(const void* p) {
    uint32_t a;
    asm("{ .reg .u64 t; cvta.to.shared.u64 t, %1; cvt.u32.u64 %0, t; }" : "=r"(a) : "l"(p));
    return a;
}
__device__ __forceinline__ void cp16(uint32_t d, const void* s) {
    asm volatile("cp.async.cg.shared.global [%0], [%1], 16;" :: "r"(d), "l"(s) : "memory");
}
#define CP_COMMIT() asm volatile("cp.async.commit_group;" ::: "memory")
#define CP_WAIT3()  asm volatile("cp.async.wait_group 3;" ::: "memory")
__device__ __forceinline__ void ldsm_x4(uint32_t* r, uint32_t a) {
    asm volatile("ldmatrix.sync.aligned.m8n8.x4.shared.b16 {%0,%1,%2,%3}, [%4];"
                 : "=r"(r[0]), "=r"(r[1]), "=r"(r[2]), "=r"(r[3]) : "r"(a));
}
__device__ __forceinline__ void mma16816(float* d, const uint32_t* a, const uint32_t* b) {
    asm volatile("mma.sync.aligned.m16n8k16.row.col.f32.f16.f16.f32 "
                 "{%0,%1,%2,%3}, {%4,%5,%6,%7}, {%8,%9}, {%0,%1,%2,%3};"
                 : "+f"(d[0]), "+f"(d[1]), "+f"(d[2]), "+f"(d[3])
                 : "r"(a[0]), "r"(a[1]), "r"(a[2]), "r"(a[3]), "r"(b[0]), "r"(b[1]));
}

// ---------------- 1) fused: LN+segsum | W^T transpose | placeholder rank ----
// 2880 blocks x 256 thr: [0,2048) ln; [2048,2816) wsplit; [2816,2880) rank.
__global__ __launch_bounds__(256) void k_ln_prep(const float* __restrict__ vis,
                                                 const float* __restrict__ gamma,
                                                 const float* __restrict__ beta,
                                                 const float* __restrict__ W,
                                                 const int* __restrict__ ids,
                                                 const int* __restrict__ phid) {
    __shared__ __align__(16) char shm[4352];
    int bx = blockIdx.x, tid = threadIdx.x;

    if (bx < 2048) {
        // ---- LayerNorm + segment sum -> fp16 ----
        float* rs  = (float*)shm;          // [8][8]
        float* rq  = rs + 64;              // [8][8]
        float* bc2 = rq + 64;              // [8][2]
        int lane = tid & 31, warp = tid >> 5;
        const float* base = vis + (size_t)bx * PPT * DV;
        int d0 = tid * 4;

        float4 x[PPT];
        #pragma unroll
        for (int p = 0; p < PPT; ++p)
            x[p] = *(const float4*)(base + p * DV + d0);

        #pragma unroll
        for (int p = 0; p < PPT; ++p) {
            float s = x[p].x + x[p].y + x[p].z + x[p].w;
            float q = x[p].x * x[p].x + x[p].y * x[p].y + x[p].z * x[p].z + x[p].w * x[p].w;
            #pragma unroll
            for (int o = 16; o > 0; o >>= 1) {
                s += __shfl_xor_sync(0xffffffffu, s, o);
                q += __shfl_xor_sync(0xffffffffu, q, o);
            }
            if (lane == 0) { rs[p * 8 + warp] = s; rq[p * 8 + warp] = q; }
        }
        __syncthreads();
        if (warp == 0) {
            int p = lane & 7, h = lane >> 3;
            float s2 = rs[p * 8 + h] + rs[p * 8 + h + 4];
            float q2 = rq[p * 8 + h] + rq[p * 8 + h + 4];
            s2 += __shfl_xor_sync(0xffffffffu, s2, 8);
            q2 += __shfl_xor_sync(0xffffffffu, q2, 8);
            s2 += __shfl_xor_sync(0xffffffffu, s2, 16);
            q2 += __shfl_xor_sync(0xffffffffu, q2, 16);
            if (lane < 8) {
                float mean = s2 * (1.f / DV);
                float var  = q2 * (1.f / DV) - mean * mean;
                bc2[p * 2 + 0] = mean;
                bc2[p * 2 + 1] = rsqrtf(var + 1e-5f);
            }
        }
        __syncthreads();

        float4 g  = *(const float4*)(gamma + d0);
        float4 be = *(const float4*)(beta  + d0);
        float a0 = 0.f, a1 = 0.f, a2 = 0.f, a3 = 0.f;
        #pragma unroll
        for (int p = 0; p < PPT; ++p) {
            float mean = bc2[p * 2 + 0], rstd = bc2[p * 2 + 1];
            a0 += (x[p].x - mean) * rstd * g.x + be.x;
            a1 += (x[p].y - mean) * rstd * g.y + be.y;
            a2 += (x[p].z - mean) * rstd * g.z + be.z;
            a3 += (x[p].w - mean) * rstd * g.w + be.w;
        }
        __half2 h01 = __floats2half2_rn(a0, a1);
        __half2 h23 = __floats2half2_rn(a2, a3);
        uint2 w;
        memcpy(&w.x, &h01, 4);
        memcpy(&w.y, &h23, 4);
        *(uint2*)(g_ah + (size_t)bx * KA + d0) = w;
    } else if (bx < 2816) {
        // ---- W [1024,768] -> W^T fp16 tile transpose ----
        float (*t)[33] = (float(*)[33])shm;
        int b2 = bx - 2048;
        int n0 = (b2 % 24) * 32, k0 = (b2 / 24) * 32;
        int tx = tid & 31, ty = tid >> 5;  // 32 x 8
        #pragma unroll
        for (int i = 0; i < 4; ++i)
            t[ty + 8 * i][tx] = W[(size_t)(k0 + ty + 8 * i) * DT + n0 + tx];
        __syncthreads();
        #pragma unroll
        for (int i = 0; i < 4; ++i) {
            int n = n0 + ty + 8 * i;
            g_bh[(size_t)n * KB + k0 + tx] = __float2half_rn(t[tx][ty + 8 * i]);
        }
    } else {
        // ---- placeholder rank (2 seq positions per thread) ----
        int* sc = (int*)shm;               // 256 ints
        int b = bx - 2816;
        int ph = phid[0];
        int i0 = ids[b * SS + 2 * tid];
        int i1 = ids[b * SS + 2 * tid + 1];
        int m0 = (i0 == ph) ? 1 : 0;
        int m1 = (i1 == ph) ? 1 : 0;
        if (tid < NSEG) g_pos[b * NSEG + tid] = -1;
        sc[tid] = m0 + m1;
        __syncthreads();
        for (int o = 1; o < 256; o <<= 1) {
            int v = (tid >= o) ? sc[tid - o] : 0;
            __syncthreads();
            sc[tid] += v;
            __syncthreads();
        }
        int pre = sc[tid] - (m0 + m1);     // exclusive prefix of pairs
        int r0 = pre + m0 - 1;
        int r1 = pre + m0 + m1 - 1;
        int rk0 = (m0 && r0 < NSEG) ? r0 : -1;
        int rk1 = (m1 && r1 < NSEG) ? r1 : -1;
        g_rank[b * SS + 2 * tid]     = rk0;
        g_rank[b * SS + 2 * tid + 1] = rk1;
        if (rk0 >= 0) g_pos[b * NSEG + rk0] = 2 * tid;
        if (rk1 >= 0) g_pos[b * NSEG + rk1] = 2 * tid + 1;
    }
}

// ---------------- 2) mma.sync fp16 GEMM, split-K=2, 192 CTAs ----------------
#define ABYTES (128 * 80)
#define BBYTES (96 * 80)
#define STGB   (ABYTES + BBYTES)
__global__ __launch_bounds__(256, 2) void k_gemm_mma() {
    extern __shared__ __align__(16) char sm[];
    uint32_t smb = smem_u32(sm);
    int tid = threadIdx.x, lane = tid & 31, wid = tid >> 5;
    int wm = wid & 3, wn = wid >> 2;
    int m0 = blockIdx.y * 128, n0 = blockIdx.x * 96;
    int z = blockIdx.z;
    int koff = z * 512;

    const __half* gA = g_ah + (size_t)m0 * KA + koff;
    const __half* gB = g_bh + (size_t)n0 * KB + koff;

    auto prefetch = [&](int i, int stg) {
        int kin = i << 5;
        uint32_t stA = smb + stg * STGB;
        uint32_t stB = stA + ABYTES;
        #pragma unroll
        for (int j = 0; j < 2; ++j) {
            int ca = tid + j * 256;
            int r = ca >> 2, c = ca & 3;
            cp16(stA + r * 80 + c * 16, gA + (size_t)r * KA + kin + c * 8);
        }
        {
            int r = tid >> 2, c = tid & 3;
            cp16(stB + r * 80 + c * 16, gB + (size_t)r * KB + kin + c * 8);
        }
        if (tid < 128) {
            int cb = tid + 256;
            int r = cb >> 2, c = cb & 3;
            cp16(stB + r * 80 + c * 16, gB + (size_t)r * KB + kin + c * 8);
        }
        CP_COMMIT();
    };

    float d[2][6][4];
    #pragma unroll
    for (int i = 0; i < 2; ++i)
        #pragma unroll
        for (int j = 0; j < 6; ++j)
            #pragma unroll
            for (int c = 0; c < 4; ++c) d[i][j][c] = 0.f;

    #pragma unroll
    for (int s = 0; s < STAGES - 1; ++s) prefetch(s, s);   // 4 pending

    int aRow = (wm * 32 + (lane & 15)) * 80 + (lane >> 4) * 16;
    int bRow = (wn * 48 + (lane & 7) + ((lane >> 4) << 3)) * 80 + ((lane >> 3) & 1) * 16;

    int stg = 0, pstg = STAGES - 1;
    for (int i = 0; i < KITER; ++i) {
        CP_WAIT3();
        __syncthreads();
        if (i + STAGES - 1 < KITER) {
            prefetch(i + STAGES - 1, pstg);
            if (++pstg == STAGES) pstg = 0;
        } else CP_COMMIT();
        uint32_t stA = smb + stg * STGB;
        uint32_t stB = stA + ABYTES;
        if (++stg == STAGES) stg = 0;
        #pragma unroll
        for (int s = 0; s < 2; ++s) {
            uint32_t a[2][4], b[3][4];
            #pragma unroll
            for (int mf = 0; mf < 2; ++mf)
                ldsm_x4(a[mf], stA + aRow + mf * 16 * 80 + s * 32);
            #pragma unroll
            for (int np = 0; np < 3; ++np)
                ldsm_x4(b[np], stB + bRow + np * 16 * 80 + s * 32);
            #pragma unroll
            for (int mf = 0; mf < 2; ++mf)
                #pragma unroll
                for (int nf = 0; nf < 6; ++nf)
                    mma16816(d[mf][nf], a[mf], &b[nf >> 1][(nf & 1) * 2]);
        }
    }

    float* outb = z ? g_part1 : g_part0;
    int grp = lane >> 2, tig = lane & 3;
    #pragma unroll
    for (int nf = 0; nf < 6; ++nf) {
        int n = n0 + wn * 48 + nf * 8 + tig * 2;
        #pragma unroll
        for (int mf = 0; mf < 2; ++mf) {
            int m = m0 + wm * 32 + mf * 16 + grp;
            *(float2*)(outb + (size_t)m * DT + n)       = make_float2(d[mf][nf][0], d[mf][nf][1]);
            *(float2*)(outb + (size_t)(m + 8) * DT + n) = make_float2(d[mf][nf][2], d[mf][nf][3]);
        }
    }
}

// ---------------- 3) text_emb: branchless gather, batch-8 loads -------------
// 2048 blocks x 384 thr. 8 LDG.128 in flight per thread before the stores.
#define TROWS 8
__global__ __launch_bounds__(384) void k_text_nonph(const float* __restrict__ wte,
                                                    const int* __restrict__ ids,
                                                    float* __restrict__ out) {
    int tid = threadIdx.x;
    int c    = tid % 192;
    int half = tid / 192;
    int base = blockIdx.x * 16 + half * TROWS;

    int rk[TROWS], id[TROWS];
    #pragma unroll
    for (int i = 0; i < TROWS; ++i) {
        rk[i] = g_rank[base + i];
        id[i] = __ldg(ids + base + i);
    }
    float4 v[TROWS];
    #pragma unroll
    for (int i = 0; i < TROWS; ++i)
        v[i] = ((const float4*)(wte + (size_t)id[i] * DT))[c];
    #pragma unroll
    for (int i = 0; i < TROWS; ++i)
        if (rk[i] < 0)
            ((float4*)out)[(size_t)(base + i) * 192 + c] = v[i];
}

// ---------------- 4) combine halves + bias -> scatter to out; pooled --------
__global__ __launch_bounds__(256) void k_combine(const float* __restrict__ bproj,
                                                 float* __restrict__ out) {
    int b = blockIdx.y, tid = threadIdx.x;
    int d = blockIdx.x * 128 + (tid & 127);
    int sg0 = tid >> 7;
    __shared__ float sp[256];
    float bias = bproj[d];
    size_t base = (size_t)b * NSEG * DT + d;
    float acc = 0.f;
    #pragma unroll
    for (int sg = sg0; sg < NSEG; sg += 2) {
        size_t idx = base + (size_t)sg * DT;
        float s = g_part0[idx] + g_part1[idx];
        acc += s;
        int pos = g_pos[b * NSEG + sg];
        if (pos >= 0)
            out[((size_t)b * SS + pos) * DT + d] = s * 0.125f + bias;
    }
    sp[tid] = acc;
    __syncthreads();
    if (tid < 128)
        g_pool[(size_t)b * DT + d] = (sp[tid] + sp[tid + 128]) * (0.125f / 32.f) + bias;
}

// ---------------- 5) sim = cos-sim / TEMP (norm fused) ----------------------
__global__ __launch_bounds__(256) void k_sim() {
    int i = blockIdx.y, jq = blockIdx.x;
    int tid = threadIdx.x, w = tid >> 5, lane = tid & 31;
    __shared__ float ni[DT];
    __shared__ float red[8];
    __shared__ float qi_s;
    if (tid < 192)
        *(float4*)(ni + tid * 4) = *(const float4*)(g_pool + (size_t)i * DT + tid * 4);
    __syncthreads();
    {
        float q = ni[tid] * ni[tid] + ni[tid + 256] * ni[tid + 256]
                + ni[tid + 512] * ni[tid + 512];
        #pragma unroll
        for (int o = 16; o > 0; o >>= 1) q += __shfl_xor_sync(0xffffffffu, q, o);
        if (lane == 0) red[w] = q;
        __syncthreads();
        if (tid == 0) {
            float s = 0.f;
            #pragma unroll
            for (int k = 0; k < 8; ++k) s += red[k];
            qi_s = s;
        }
        __syncthreads();
    }
    float qi = qi_s;
    #pragma unroll
    for (int jj = 0; jj < 2; ++jj) {
        int j = jq * 16 + w * 2 + jj;
        const float4* nj = (const float4*)(g_pool + (size_t)j * DT);
        float s = 0.f, qj = 0.f;
        #pragma unroll
        for (int it = 0; it < 6; ++it) {
            int d4 = lane + it * 32;
            float4 bb = nj[d4];
            float4 aa = *(const float4*)(ni + d4 * 4);
            s  += aa.x * bb.x + aa.y * bb.y + aa.z * bb.z + aa.w * bb.w;
            qj += bb.x * bb.x + bb.y * bb.y + bb.z * bb.z + bb.w * bb.w;
        }
        #pragma unroll
        for (int o = 16; o > 0; o >>= 1) {
            s  += __shfl_xor_sync(0xffffffffu, s, o);
            qj += __shfl_xor_sync(0xffffffffu, qj, o);
        }
        if (lane == 0)
            g_sim[i * NB + j] = s * rsqrtf(qi * qj) * (1.f / 0.07f);
    }
}

// ---------------- 6) symmetric InfoNCE loss ---------------------------------
__global__ void k_loss(float* __restrict__ out) {
    int i = threadIdx.x;
    __shared__ float red[64];
    float diag = g_sim[i * NB + i];
    float m = -1e30f;
    for (int j = 0; j < NB; ++j) m = fmaxf(m, g_sim[i * NB + j]);
    float se = 0.f;
    for (int j = 0; j < NB; ++j) se += expf(g_sim[i * NB + j] - m);
    float rl = (m + logf(se)) - diag;
    float mc = -1e30f;
    for (int j = 0; j < NB; ++j) mc = fmaxf(mc, g_sim[j * NB + i]);
    float sc = 0.f;
    for (int j = 0; j < NB; ++j) sc += expf(g_sim[j * NB + i] - mc);
    float cl = (mc + logf(sc)) - diag;
    red[i] = rl + cl;
    __syncthreads();
    #pragma unroll
    for (int o = 32; o > 0; o >>= 1) {
        if (i < o) red[i] += red[i + o];
        __syncthreads();
    }
    if (i == 0) out[0] = red[0] * (0.5f / NB);
}

// ---------------- launch (single stream; pipeline is serial anyway) ---------
extern "C" void kernel_launch(void* const* d_in, const int* in_sizes, int n_in,
                              void* d_out, int out_size) {
    const float* vis   = (const float*)d_in[0];
    const float* gamma = (const float*)d_in[1];
    const float* beta  = (const float*)d_in[2];
    const float* W     = (const float*)d_in[3];
    const float* bproj = (const float*)d_in[4];
    const float* wte   = (const float*)d_in[5];
    const int*   ids   = (const int*)d_in[6];
    const int*   phid  = (const int*)d_in[7];
    float* out = (float*)d_out;

    cudaFuncSetAttribute(k_gemm_mma, cudaFuncAttributeMaxDynamicSharedMemorySize,
                         STAGES * STGB);

    k_ln_prep<<<2880, 256>>>(vis, gamma, beta, W, ids, phid);            // call 1
    k_gemm_mma<<<dim3(DT / 96, MTOT / 128, 2), 256, STAGES * STGB>>>();  // call 2
    k_text_nonph<<<NB * SS / 16, 384>>>(wte, ids, out);                  // call 3
    k_combine<<<dim3(6, NB), 256>>>(bproj, out);                         // call 4 (profiled)
    k_sim<<<dim3(4, NB), 256>>>();                                       // call 5
    k_loss<<<1, 64>>>(out + (size_t)out_size - 1);                       // call 6
}